// round 9
// baseline (speedup 1.0000x reference)
#include <cuda_runtime.h>
#include <cuda_fp16.h>
#include <cuda_bf16.h>

#define NN 100000
#define DIMV 64
#define EE 1600000
#define CHUNK 512
#define NCHMAX ((NN + CHUNK - 1) / CHUNK)   // 196
#define FULL 0xffffffffu

// Scratch (__device__ globals per allocation-free rule)
__device__ __align__(256) float  g_norm[NN];
__device__ __align__(256) int    g_cnt[NN];      // in-degree counts
__device__ __align__(256) int    g_off[NN];      // CSR offsets (exclusive scan)
__device__ __align__(256) int    g_fill[NN];     // placement cursors
__device__ __align__(256) int    g_csum[NCHMAX]; // per-chunk count sums
__device__ __align__(256) float2 g_edges[EE];    // dst-sorted {src_bits, w}
__device__ __align__(256) __half g_tmpA[NN * DIMV];  // h_cur * norm (fp16)
__device__ __align__(256) __half g_tmpB[NN * DIMV];

// ---------------------------------------------------------------------------
// K0: zero cnt + fill
// ---------------------------------------------------------------------------
__global__ void k_zero(int N) {
    for (int i = blockIdx.x * blockDim.x + threadIdx.x; i < N;
         i += gridDim.x * blockDim.x) {
        g_cnt[i]  = 0;
        g_fill[i] = 0;
    }
}

// ---------------------------------------------------------------------------
// K1: dst histogram only (4 edges/thread). Weighted degree moved to k_init.
// ---------------------------------------------------------------------------
__global__ void k_hist(const int* __restrict__ dst, int E) {
    int t = blockIdx.x * blockDim.x + threadIdx.x;
    int e = t * 4;
    if (e + 3 < E) {
        int4 dv = *(const int4*)&dst[e];
        atomicAdd(&g_cnt[dv.x], 1);
        atomicAdd(&g_cnt[dv.y], 1);
        atomicAdd(&g_cnt[dv.z], 1);
        atomicAdd(&g_cnt[dv.w], 1);
    } else {
        for (; e < E; ++e) atomicAdd(&g_cnt[dst[e]], 1);
    }
}

// ---------------------------------------------------------------------------
// Scan step 1: per-chunk sums of g_cnt (warp shuffles)
// ---------------------------------------------------------------------------
__global__ void k_scan1(int N) {
    __shared__ int ws[16];
    int b = blockIdx.x, t = threadIdx.x;
    int i = b * CHUNK + t;
    int v = (i < N) ? g_cnt[i] : 0;
    #pragma unroll
    for (int s = 16; s; s >>= 1) v += __shfl_down_sync(FULL, v, s);
    if ((t & 31) == 0) ws[t >> 5] = v;
    __syncthreads();
    if (t == 0) {
        int x = 0;
        #pragma unroll
        for (int k = 0; k < 16; k++) x += ws[k];
        g_csum[b] = x;
    }
}

// ---------------------------------------------------------------------------
// Scan step 2 (fused base): each block reduces g_csum[0..b) for its base,
// then does an intra-chunk exclusive scan of g_cnt -> g_off. No k_scan2.
// ---------------------------------------------------------------------------
__global__ void k_scan3(int N) {
    __shared__ int wbase[16];
    __shared__ int wtot[16];
    __shared__ int s_base;
    int b = blockIdx.x, t = threadIdx.x;
    int warp = t >> 5, lane = t & 31;

    // ---- base = sum of previous chunk sums (b <= 195 < 512 threads) ----
    int bv = (t < b) ? g_csum[t] : 0;
    #pragma unroll
    for (int s = 16; s; s >>= 1) bv += __shfl_down_sync(FULL, bv, s);
    if (lane == 0) wbase[warp] = bv;
    __syncthreads();
    if (t == 0) {
        int x = 0;
        #pragma unroll
        for (int k = 0; k < 16; k++) x += wbase[k];
        s_base = x;
    }

    // ---- intra-chunk exclusive scan (warp shuffle scan) ----
    int i = b * CHUNK + t;
    int x = (i < N) ? g_cnt[i] : 0;
    int incl = x;
    #pragma unroll
    for (int d = 1; d < 32; d <<= 1) {
        int y = __shfl_up_sync(FULL, incl, d);
        if (lane >= d) incl += y;
    }
    if (lane == 31) wtot[warp] = incl;
    __syncthreads();
    if (t < 16) {   // exclusive scan of 16 warp totals within one warp
        int wv = wtot[t];
        int winc = wv;
        #pragma unroll
        for (int d = 1; d < 16; d <<= 1) {
            int y = __shfl_up_sync(0xffffu, winc, d);
            if (t >= d) winc += y;
        }
        wtot[t] = winc - wv;   // exclusive
    }
    __syncthreads();
    if (i < N) g_off[i] = s_base + wtot[warp] + (incl - x);
}

// ---------------------------------------------------------------------------
// K_place: counting-sort edges by dst into g_edges = {src_bits, w}
// ---------------------------------------------------------------------------
__global__ void k_place(const float* __restrict__ w,
                        const int* __restrict__ src,
                        const int* __restrict__ dst, int E) {
    int e = blockIdx.x * blockDim.x + threadIdx.x;
    if (e >= E) return;
    int d = dst[e];
    int p = g_off[d] + atomicAdd(&g_fill[d], 1);
    g_edges[p] = make_float2(__int_as_float(src[e]), w[e]);
}

// ---------------------------------------------------------------------------
// K_init: warp per node. deg = sum of w over sorted in-edges (coalesced, no
// atomics); norm = rsqrt(max(deg,1)); out = h/3; tmpA = half(h*norm).
// ---------------------------------------------------------------------------
__global__ void k_init(const float* __restrict__ h, float* __restrict__ out,
                       int N) {
    int gw = (blockIdx.x * blockDim.x + threadIdx.x) >> 5;
    if (gw >= N) return;
    int lane = threadIdx.x & 31;
    int off = g_off[gw];
    int cnt = g_cnt[gw];

    float ws = 0.0f;
    for (int j = lane; j < cnt; j += 32) ws += g_edges[off + j].y;
    #pragma unroll
    for (int s = 16; s; s >>= 1) ws += __shfl_down_sync(FULL, ws, s);
    float deg = __shfl_sync(FULL, ws, 0);
    float nrm = rsqrtf(fmaxf(deg, 1.0f));
    if (lane == 0) g_norm[gw] = nrm;

    int idx = gw * DIMV + lane * 2;
    float2 hv = *(const float2*)&h[idx];
    const float third = 1.0f / 3.0f;
    *(float2*)&out[idx] = make_float2(hv.x * third, hv.y * third);
    *(__half2*)&g_tmpA[idx] = __floats2half2_rn(hv.x * nrm, hv.y * nrm);
}

// ---------------------------------------------------------------------------
// K_gather<LAST>: warp per node, 2 edges processed concurrently.
// Lane (grp=lane>>4, sub=lane&15) handles dims [4*sub, 4*sub+4) of edge 2k+grp.
// Cross-group combine via shfl_down(16); epilogue by grp 0 lanes (float4).
// ---------------------------------------------------------------------------
template <bool LAST>
__global__ void k_gather(float* __restrict__ out, int N) {
    const __half* __restrict__ tsrc = LAST ? g_tmpB : g_tmpA;
    int gw = (blockIdx.x * blockDim.x + threadIdx.x) >> 5;
    if (gw >= N) return;
    int lane = threadIdx.x & 31;
    int grp = lane >> 4;
    int sub = lane & 15;
    int off = g_off[gw];
    int dg  = g_cnt[gw];
    float a0 = 0.f, a1 = 0.f, a2 = 0.f, a3 = 0.f;

    for (int base = 0; base < dg; base += 32) {
        int m = dg - base; if (m > 32) m = 32;
        float ex = 0.0f, ey = 0.0f;
        if (lane < m) {
            float2 ed = g_edges[off + base + lane];
            ex = ed.x; ey = ed.y;
        }
        int pairs = (m + 1) >> 1;
        for (int k = 0; k < pairs; k++) {
            int j = 2 * k + grp;
            int   s  = __float_as_int(__shfl_sync(FULL, ex, j));
            float sw = __shfl_sync(FULL, ey, j);
            if (j < m) {
                uint2 hv = *(const uint2*)&tsrc[s * DIMV + sub * 4];
                float2 v0 = __half22float2(*(__half2*)&hv.x);
                float2 v1 = __half22float2(*(__half2*)&hv.y);
                a0 = fmaf(v0.x, sw, a0);
                a1 = fmaf(v0.y, sw, a1);
                a2 = fmaf(v1.x, sw, a2);
                a3 = fmaf(v1.y, sw, a3);
            }
        }
    }

    // combine the two edge-groups (same dims, different edges)
    a0 += __shfl_down_sync(FULL, a0, 16);
    a1 += __shfl_down_sync(FULL, a1, 16);
    a2 += __shfl_down_sync(FULL, a2, 16);
    a3 += __shfl_down_sync(FULL, a3, 16);

    float nrm = g_norm[gw];
    if (grp == 0) {
        int idx = gw * DIMV + sub * 4;
        const float third = 1.0f / 3.0f;
        float h0 = a0 * nrm, h1 = a1 * nrm, h2 = a2 * nrm, h3 = a3 * nrm;
        float4 o = *(float4*)&out[idx];
        o.x += h0 * third; o.y += h1 * third;
        o.z += h2 * third; o.w += h3 * third;
        *(float4*)&out[idx] = o;
        if (!LAST) {
            __half2 p0 = __floats2half2_rn(h0 * nrm, h1 * nrm);
            __half2 p1 = __floats2half2_rn(h2 * nrm, h3 * nrm);
            uint2 pk;
            pk.x = *(unsigned*)&p0;
            pk.y = *(unsigned*)&p1;
            *(uint2*)&g_tmpB[idx] = pk;
        }
    }
}

// ---------------------------------------------------------------------------
// Launch
// ---------------------------------------------------------------------------
extern "C" void kernel_launch(void* const* d_in, const int* in_sizes, int n_in,
                              void* d_out, int out_size) {
    const float* h   = (const float*)d_in[0];
    const float* w   = (const float*)d_in[1];
    const int*   src = (const int*)d_in[2];
    const int*   dst = (const int*)d_in[3];
    float* out = (float*)d_out;

    const int N = in_sizes[0] / DIMV;   // 100000
    const int E = in_sizes[1];          // 1600000
    const int nch = (N + CHUNK - 1) / CHUNK;

    const int TB = 256;

    // CSR build
    k_zero<<<128, TB>>>(N);
    int hthreads = (E + 3) / 4;
    k_hist<<<(hthreads + TB - 1) / TB, TB>>>(dst, E);
    k_scan1<<<nch, CHUNK>>>(N);
    k_scan3<<<nch, CHUNK>>>(N);
    k_place<<<(E + TB - 1) / TB, TB>>>(w, src, dst, E);

    // norm (from sorted edges) + layer-0 contribution
    int wblocks = (N + 7) / 8;
    k_init<<<wblocks, TB>>>(h, out, N);

    // Layers (warp per node, 8 warps/block)
    k_gather<false><<<wblocks, TB>>>(out, N);   // reads tmpA, writes tmpB
    k_gather<true><<<wblocks, TB>>>(out, N);    // reads tmpB
}

// round 10
// speedup vs baseline: 1.4644x; 1.4644x over previous
#include <cuda_runtime.h>
#include <cuda_fp16.h>
#include <cuda_bf16.h>

#define NN 100000
#define DIMV 64
#define EE 1600000
#define CHUNK 512
#define NCHMAX ((NN + CHUNK - 1) / CHUNK)   // 196
#define FULL 0xffffffffu

// Scratch (__device__ globals per allocation-free rule)
__device__ __align__(256) float  g_norm[NN];
__device__ __align__(256) int    g_cnt[NN];      // in-degree counts
__device__ __align__(256) int    g_off[NN];      // CSR offsets (exclusive scan)
__device__ __align__(256) int    g_fill[NN];     // placement cursors
__device__ __align__(256) int    g_csum[NCHMAX]; // per-chunk count sums
__device__ __align__(256) float2 g_edges[EE];    // dst-sorted {src_bits, w}
__device__ __align__(256) __half g_tmpA[NN * DIMV];  // h_cur * norm (fp16)
__device__ __align__(256) __half g_tmpB[NN * DIMV];

// ---------------------------------------------------------------------------
// K0: zero cnt + fill
// ---------------------------------------------------------------------------
__global__ void k_zero(int N) {
    for (int i = blockIdx.x * blockDim.x + threadIdx.x; i < N;
         i += gridDim.x * blockDim.x) {
        g_cnt[i]  = 0;
        g_fill[i] = 0;
    }
}

// ---------------------------------------------------------------------------
// K1: dst histogram only (4 edges/thread). Weighted degree done in k_init.
// ---------------------------------------------------------------------------
__global__ void k_hist(const int* __restrict__ dst, int E) {
    int t = blockIdx.x * blockDim.x + threadIdx.x;
    int e = t * 4;
    if (e + 3 < E) {
        int4 dv = *(const int4*)&dst[e];
        atomicAdd(&g_cnt[dv.x], 1);
        atomicAdd(&g_cnt[dv.y], 1);
        atomicAdd(&g_cnt[dv.z], 1);
        atomicAdd(&g_cnt[dv.w], 1);
    } else {
        for (; e < E; ++e) atomicAdd(&g_cnt[dst[e]], 1);
    }
}

// ---------------------------------------------------------------------------
// Scan step 1: per-chunk sums of g_cnt (warp shuffles)
// ---------------------------------------------------------------------------
__global__ void k_scan1(int N) {
    __shared__ int ws[16];
    int b = blockIdx.x, t = threadIdx.x;
    int i = b * CHUNK + t;
    int v = (i < N) ? g_cnt[i] : 0;
    #pragma unroll
    for (int s = 16; s; s >>= 1) v += __shfl_down_sync(FULL, v, s);
    if ((t & 31) == 0) ws[t >> 5] = v;
    __syncthreads();
    if (t == 0) {
        int x = 0;
        #pragma unroll
        for (int k = 0; k < 16; k++) x += ws[k];
        g_csum[b] = x;
    }
}

// ---------------------------------------------------------------------------
// Scan step 2 (fused base): each block reduces g_csum[0..b) for its base,
// then does an intra-chunk exclusive scan of g_cnt -> g_off.
// ---------------------------------------------------------------------------
__global__ void k_scan3(int N) {
    __shared__ int wbase[16];
    __shared__ int wtot[16];
    __shared__ int s_base;
    int b = blockIdx.x, t = threadIdx.x;
    int warp = t >> 5, lane = t & 31;

    // base = sum of previous chunk sums (b <= 195 < 512 threads)
    int bv = (t < b) ? g_csum[t] : 0;
    #pragma unroll
    for (int s = 16; s; s >>= 1) bv += __shfl_down_sync(FULL, bv, s);
    if (lane == 0) wbase[warp] = bv;
    __syncthreads();
    if (t == 0) {
        int x = 0;
        #pragma unroll
        for (int k = 0; k < 16; k++) x += wbase[k];
        s_base = x;
    }

    // intra-chunk exclusive scan (warp shuffle scan)
    int i = b * CHUNK + t;
    int x = (i < N) ? g_cnt[i] : 0;
    int incl = x;
    #pragma unroll
    for (int d = 1; d < 32; d <<= 1) {
        int y = __shfl_up_sync(FULL, incl, d);
        if (lane >= d) incl += y;
    }
    if (lane == 31) wtot[warp] = incl;
    __syncthreads();
    if (t < 16) {
        int wv = wtot[t];
        int winc = wv;
        #pragma unroll
        for (int d = 1; d < 16; d <<= 1) {
            int y = __shfl_up_sync(0xffffu, winc, d);
            if (t >= d) winc += y;
        }
        wtot[t] = winc - wv;
    }
    __syncthreads();
    if (i < N) g_off[i] = s_base + wtot[warp] + (incl - x);
}

// ---------------------------------------------------------------------------
// K_place: counting-sort edges by dst into g_edges = {src_bits, w}
// ---------------------------------------------------------------------------
__global__ void k_place(const float* __restrict__ w,
                        const int* __restrict__ src,
                        const int* __restrict__ dst, int E) {
    int e = blockIdx.x * blockDim.x + threadIdx.x;
    if (e >= E) return;
    int d = dst[e];
    int p = g_off[d] + atomicAdd(&g_fill[d], 1);
    g_edges[p] = make_float2(__int_as_float(src[e]), w[e]);
}

// ---------------------------------------------------------------------------
// K_init: warp per node. deg = sum of w over sorted in-edges (coalesced, no
// atomics); norm = rsqrt(max(deg,1)); out = h/3; tmpA = half(h*norm).
// ---------------------------------------------------------------------------
__global__ void k_init(const float* __restrict__ h, float* __restrict__ out,
                       int N) {
    int gw = (blockIdx.x * blockDim.x + threadIdx.x) >> 5;
    if (gw >= N) return;
    int lane = threadIdx.x & 31;
    int off = g_off[gw];
    int cnt = g_cnt[gw];

    float ws = 0.0f;
    for (int j = lane; j < cnt; j += 32) ws += g_edges[off + j].y;
    #pragma unroll
    for (int s = 16; s; s >>= 1) ws += __shfl_down_sync(FULL, ws, s);
    float deg = __shfl_sync(FULL, ws, 0);
    float nrm = rsqrtf(fmaxf(deg, 1.0f));
    if (lane == 0) g_norm[gw] = nrm;

    int idx = gw * DIMV + lane * 2;
    float2 hv = *(const float2*)&h[idx];
    const float third = 1.0f / 3.0f;
    *(float2*)&out[idx] = make_float2(hv.x * third, hv.y * third);
    *(__half2*)&g_tmpA[idx] = __floats2half2_rn(hv.x * nrm, hv.y * nrm);
}

// ---------------------------------------------------------------------------
// K_gather<LAST>: warp per node (R8 structure — unrolled 32-edge fast path).
//   sum = sum_{e in in(n)} half(tmp_src[src_e]) * w_e   (fp32 accum)
//   h   = sum * norm;  out += h/3;  if !LAST: tmpB = half(h * norm)
// ---------------------------------------------------------------------------
template <bool LAST>
__global__ void k_gather(float* __restrict__ out, int N) {
    const __half* __restrict__ tsrc = LAST ? g_tmpB : g_tmpA;
    int gw = (blockIdx.x * blockDim.x + threadIdx.x) >> 5;
    if (gw >= N) return;
    int lane = threadIdx.x & 31;
    int off = g_off[gw];
    int dg  = g_cnt[gw];
    float ax = 0.0f, ay = 0.0f;

    for (int base = 0; base < dg; base += 32) {
        int m = dg - base; if (m > 32) m = 32;
        float ex = 0.0f, ey = 0.0f;
        if (lane < m) {
            float2 ed = g_edges[off + base + lane];
            ex = ed.x; ey = ed.y;
        }
        if (m == 32) {
            #pragma unroll
            for (int k = 0; k < 32; k++) {
                int   s  = __float_as_int(__shfl_sync(FULL, ex, k));
                float sw = __shfl_sync(FULL, ey, k);
                __half2 hv = *(const __half2*)&tsrc[s * DIMV + lane * 2];
                float2 v = __half22float2(hv);
                ax = fmaf(v.x, sw, ax);
                ay = fmaf(v.y, sw, ay);
            }
        } else {
            for (int k = 0; k < m; k++) {
                int   s  = __float_as_int(__shfl_sync(FULL, ex, k));
                float sw = __shfl_sync(FULL, ey, k);
                __half2 hv = *(const __half2*)&tsrc[s * DIMV + lane * 2];
                float2 v = __half22float2(hv);
                ax = fmaf(v.x, sw, ax);
                ay = fmaf(v.y, sw, ay);
            }
        }
    }

    float nrm = g_norm[gw];
    float hx = ax * nrm, hy = ay * nrm;
    int idx = gw * DIMV + lane * 2;
    const float third = 1.0f / 3.0f;
    float2 o = *(float2*)&out[idx];
    o.x += hx * third; o.y += hy * third;
    *(float2*)&out[idx] = o;
    if (!LAST) {
        *(__half2*)&g_tmpB[idx] = __floats2half2_rn(hx * nrm, hy * nrm);
    }
}

// ---------------------------------------------------------------------------
// Launch
// ---------------------------------------------------------------------------
extern "C" void kernel_launch(void* const* d_in, const int* in_sizes, int n_in,
                              void* d_out, int out_size) {
    const float* h   = (const float*)d_in[0];
    const float* w   = (const float*)d_in[1];
    const int*   src = (const int*)d_in[2];
    const int*   dst = (const int*)d_in[3];
    float* out = (float*)d_out;

    const int N = in_sizes[0] / DIMV;   // 100000
    const int E = in_sizes[1];          // 1600000
    const int nch = (N + CHUNK - 1) / CHUNK;

    const int TB = 256;

    // CSR build
    k_zero<<<128, TB>>>(N);
    int hthreads = (E + 3) / 4;
    k_hist<<<(hthreads + TB - 1) / TB, TB>>>(dst, E);
    k_scan1<<<nch, CHUNK>>>(N);
    k_scan3<<<nch, CHUNK>>>(N);
    k_place<<<(E + TB - 1) / TB, TB>>>(w, src, dst, E);

    // norm (from sorted edges) + layer-0 contribution
    int wblocks = (N + 7) / 8;
    k_init<<<wblocks, TB>>>(h, out, N);

    // Layers (warp per node, 8 warps/block)
    k_gather<false><<<wblocks, TB>>>(out, N);   // reads tmpA, writes tmpB
    k_gather<true><<<wblocks, TB>>>(out, N);    // reads tmpB
}